// round 3
// baseline (speedup 1.0000x reference)
#include <cuda_runtime.h>
#include <float.h>

#define N_PTS 131072
#define K_EMB 1024
#define D_DIM 64
#define TE    128          // embeddings per smem tile
#define BLOCK 128

#define DECAY 0.99f
#define ONE_MINUS_DECAY (1.0f - 0.99f)
#define EPSV 1e-5f

// packed f32x2 fma: acc = a*b + acc  (componentwise, exact fp32 per lane)
#define FMA2(acc, a, b) \
    asm("fma.rn.f32x2 %0, %1, %2, %0;" : "+l"(acc) : "l"(a), "l"(b))

__device__ __forceinline__ float f32x2_hsum(unsigned long long v) {
    unsigned int lo, hi;
    asm("mov.b64 {%0, %1}, %2;" : "=r"(lo), "=r"(hi) : "l"(v));
    return __uint_as_float(lo) + __uint_as_float(hi);
}

// -------- scratch (device globals: no allocation allowed) --------
__device__ float g_counts[K_EMB];
__device__ float g_embed_sum[K_EMB * D_DIM];
__device__ float g_enorm[K_EMB];
__device__ float g_loss_sum;

// -------- prep: zero scratch, precompute ||e||^2 --------
__global__ void prep_kernel(const float* __restrict__ emb) {
    int t = blockIdx.x * blockDim.x + threadIdx.x;   // 65536 threads
    if (t < K_EMB * D_DIM) g_embed_sum[t] = 0.f;
    if (t < K_EMB) {
        g_counts[t] = 0.f;
        const float4* row = (const float4*)(emb + (size_t)t * D_DIM);
        float s = 0.f;
        #pragma unroll
        for (int q = 0; q < 16; q++) {
            float4 v = row[q];
            s += v.x * v.x + v.y * v.y + v.z * v.z + v.w * v.w;
        }
        g_enorm[t] = s;
    }
    if (t == 0) g_loss_sum = 0.f;
}

// -------- main: argmin + gather + segment-sum atomics + loss --------
__global__ __launch_bounds__(BLOCK) void vq_main(
    const float* __restrict__ z, const float* __restrict__ emb,
    float* __restrict__ out_zq, float* __restrict__ out_idx)
{
    __shared__ __align__(16) float semb[TE * D_DIM];
    __shared__ float snorm[TE];
    __shared__ float sred[BLOCK];

    const int pt = blockIdx.x * BLOCK + threadIdx.x;

    // z row -> 16 x ulonglong2 = 256 B = 64 floats = 32 f32x2 operands
    ulonglong2 zr[16];
    {
        const ulonglong2* zrow = (const ulonglong2*)(z + (size_t)pt * D_DIM);
        #pragma unroll
        for (int q = 0; q < 16; q++) zr[q] = zrow[q];
    }

    float best = FLT_MAX;
    int bi = 0;

    for (int t0 = 0; t0 < K_EMB; t0 += TE) {
        __syncthreads();
        // cooperative coalesced tile load: TE*64 floats = 2048 float4
        {
            const float4* src = (const float4*)(emb + (size_t)t0 * D_DIM);
            float4* dst = (float4*)semb;
            #pragma unroll
            for (int q = 0; q < (TE * D_DIM / 4) / BLOCK; q++)   // 16
                dst[q * BLOCK + threadIdx.x] = src[q * BLOCK + threadIdx.x];
            if (threadIdx.x < TE) snorm[threadIdx.x] = g_enorm[t0 + threadIdx.x];
        }
        __syncthreads();

        #pragma unroll 2
        for (int e = 0; e < TE; e++) {
            const ulonglong2* er = (const ulonglong2*)(semb + e * D_DIM);
            // 4 independent f32x2 accumulator chains (8 partial sums)
            unsigned long long a0 = 0ull, a1 = 0ull, a2 = 0ull, a3 = 0ull;
            #pragma unroll
            for (int q = 0; q < 16; q += 2) {
                ulonglong2 ev0 = er[q];       // LDS.128 broadcast, conflict-free
                ulonglong2 ev1 = er[q + 1];
                FMA2(a0, ev0.x, zr[q].x);
                FMA2(a1, ev0.y, zr[q].y);
                FMA2(a2, ev1.x, zr[q + 1].x);
                FMA2(a3, ev1.y, zr[q + 1].y);
            }
            float dot = (f32x2_hsum(a0) + f32x2_hsum(a1))
                      + (f32x2_hsum(a2) + f32x2_hsum(a3));
            float score = snorm[e] - 2.f * dot;
            if (score < best) { best = score; bi = t0 + e; }
        }
    }

    // ---- epilogue ----
    out_idx[pt] = (float)bi;

    const float4* qrow = (const float4*)(emb + (size_t)bi * D_DIM);
    float4* orow = (float4*)(out_zq + (size_t)pt * D_DIM);
    const float4* zrow4 = (const float4*)(z + (size_t)pt * D_DIM);
    float* esum = g_embed_sum + (size_t)bi * D_DIM;

    float lsum = 0.f;
    #pragma unroll
    for (int q = 0; q < 16; q++) {
        float4 qv = qrow[q];
        float4 zv = zrow4[q];
        orow[q] = qv;
        float dx = zv.x - qv.x, dy = zv.y - qv.y;
        float dz2 = zv.z - qv.z, dw = zv.w - qv.w;
        lsum += dx * dx + dy * dy + dz2 * dz2 + dw * dw;
        atomicAdd(esum + q * 4 + 0, zv.x);
        atomicAdd(esum + q * 4 + 1, zv.y);
        atomicAdd(esum + q * 4 + 2, zv.z);
        atomicAdd(esum + q * 4 + 3, zv.w);
    }
    atomicAdd(&g_counts[bi], 1.f);

    // block-reduce loss, one global atomic per CTA
    sred[threadIdx.x] = lsum;
    __syncthreads();
    for (int s = BLOCK / 2; s > 0; s >>= 1) {
        if (threadIdx.x < s) sred[threadIdx.x] += sred[threadIdx.x + s];
        __syncthreads();
    }
    if (threadIdx.x == 0) atomicAdd(&g_loss_sum, sred[0]);
}

// -------- finalize: EMA updates, normalization, loss mean --------
__global__ __launch_bounds__(1024) void finalize_kernel(
    const float* __restrict__ cluster_size, const float* __restrict__ ema,
    float* __restrict__ out_loss, float* __restrict__ out_nemb,
    float* __restrict__ out_ncs, float* __restrict__ out_nema)
{
    __shared__ float sred[1024];
    const int t = threadIdx.x;   // one CTA, 1024 threads (== K)

    float c = cluster_size[t] * DECAY + ONE_MINUS_DECAY * g_counts[t];
    out_ncs[t] = c;
    sred[t] = c;
    __syncthreads();
    for (int s = 512; s > 0; s >>= 1) {
        if (t < s) sred[t] += sred[t + s];
        __syncthreads();
    }
    float n = sred[0];
    float cs = (c + EPSV) / (n + (float)K_EMB * EPSV) * n;
    float inv = 1.f / cs;

    #pragma unroll 4
    for (int q = 0; q < D_DIM; q++) {
        int idx = t * D_DIM + q;
        float s = ema[idx] * DECAY + ONE_MINUS_DECAY * g_embed_sum[idx];
        out_nema[idx] = s;
        out_nemb[idx] = s * inv;
    }
    if (t == 0) out_loss[0] = g_loss_sum / (float)((size_t)N_PTS * D_DIM);
}

// -------- launch --------
extern "C" void kernel_launch(void* const* d_in, const int* in_sizes, int n_in,
                              void* d_out, int out_size) {
    const float* z   = (const float*)d_in[0];
    const float* emb = (const float*)d_in[1];
    const float* cs  = (const float*)d_in[2];
    const float* ema = (const float*)d_in[3];

    float* out      = (float*)d_out;
    float* out_zq   = out;                               // N*D
    float* out_loss = out + (size_t)N_PTS * D_DIM;       // 1
    float* out_idx  = out_loss + 1;                      // N
    float* out_nemb = out_idx + N_PTS;                   // K*D
    float* out_ncs  = out_nemb + (size_t)K_EMB * D_DIM;  // K
    float* out_nema = out_ncs + K_EMB;                   // K*D

    prep_kernel<<<256, 256>>>(emb);
    vq_main<<<N_PTS / BLOCK, BLOCK>>>(z, emb, out_zq, out_idx);
    finalize_kernel<<<1, 1024>>>(cs, ema, out_loss, out_nemb, out_ncs, out_nema);
}

// round 4
// speedup vs baseline: 1.6091x; 1.6091x over previous
#include <cuda_runtime.h>
#include <float.h>

#define N_PTS 131072
#define K_EMB 1024
#define D_DIM 64
#define MT    64           // points per CTA
#define NT    64           // embeddings per chunk
#define NCHUNK (K_EMB / NT)
#define BLOCK 128

#define DECAY 0.99f
#define ONE_MINUS_DECAY (1.0f - 0.99f)
#define EPSV 1e-5f

// packed f32x2 fma: acc = a*b + acc (componentwise, exact fp32 per lane)
#define FMA2(acc, a, b) \
    asm("fma.rn.f32x2 %0, %1, %2, %0;" : "+l"(acc) : "l"(a), "l"(b))

__device__ __forceinline__ float f32x2_hsum(unsigned long long v) {
    unsigned int lo, hi;
    asm("mov.b64 {%0, %1}, %2;" : "=r"(lo), "=r"(hi) : "l"(v));
    return __uint_as_float(lo) + __uint_as_float(hi);
}

// 16B-unit XOR swizzle within a 64-float row: unit u (0..15), key from row id.
__device__ __forceinline__ int swz(int u, int key) {
    return (u & 8) | ((u ^ key) & 7);
}

// -------- scratch (device globals) --------
__device__ float g_counts[K_EMB];
__device__ float g_embed_sum[K_EMB * D_DIM];
__device__ float g_enorm[K_EMB];
__device__ float g_loss_sum;

// -------- prep: zero scratch, precompute ||e||^2 --------
__global__ void prep_kernel(const float* __restrict__ emb) {
    int t = blockIdx.x * blockDim.x + threadIdx.x;   // 65536 threads
    if (t < K_EMB * D_DIM) g_embed_sum[t] = 0.f;
    if (t < K_EMB) {
        g_counts[t] = 0.f;
        const float4* row = (const float4*)(emb + (size_t)t * D_DIM);
        float s = 0.f;
        #pragma unroll
        for (int q = 0; q < 16; q++) {
            float4 v = row[q];
            s += v.x * v.x + v.y * v.y + v.z * v.z + v.w * v.w;
        }
        g_enorm[t] = s;
    }
    if (t == 0) g_loss_sum = 0.f;
}

// -------- main: tiled scores + argmin + epilogue --------
__global__ __launch_bounds__(BLOCK, 3) void vq_main(
    const float* __restrict__ z, const float* __restrict__ emb,
    float* __restrict__ out_zq, float* __restrict__ out_idx)
{
    __shared__ __align__(16) float z_s[MT * D_DIM];   // swizzled, key=(m>>2)&7
    __shared__ __align__(16) float e_s[NT * D_DIM];   // swizzled, key=(n>>3)&7
    __shared__ int   s_bidx[MT];
    __shared__ float sred[BLOCK];

    const int t  = threadIdx.x;
    const int tx = t & 7;          // n-direction: owns n = tx*8 .. tx*8+7
    const int ty = t >> 3;         // m-direction: owns m = ty*4 .. ty*4+3
    const int pt0 = blockIdx.x * MT;

    // ---- load z tile (swizzled). 1024 16B-units, 8 per thread ----
    {
        const float4* zg = (const float4*)(z + (size_t)pt0 * D_DIM);
        #pragma unroll
        for (int r = 0; r < 8; r++) {
            int id = t + BLOCK * r;
            int m = id >> 4, u = id & 15;
            float4 v = zg[id];
            *(float4*)(z_s + m * D_DIM + swz(u, m >> 2) * 4) = v;
        }
    }

    float best[4]; int bidx[4];
    #pragma unroll
    for (int i = 0; i < 4; i++) { best[i] = FLT_MAX; bidx[i] = 0; }

    for (int c = 0; c < NCHUNK; c++) {
        __syncthreads();   // also covers z_s store at c==0
        // ---- load e chunk (swizzled) ----
        {
            const float4* eg = (const float4*)(emb + (size_t)c * NT * D_DIM);
            #pragma unroll
            for (int r = 0; r < 8; r++) {
                int id = t + BLOCK * r;
                int n = id >> 4, u = id & 15;
                float4 v = eg[id];
                *(float4*)(e_s + n * D_DIM + swz(u, n >> 3) * 4) = v;
            }
        }
        // prefetch ||e||^2 for my 8 n's (consumed after k-loop)
        float4 en0 = *(const float4*)(g_enorm + c * NT + tx * 8);
        float4 en1 = *(const float4*)(g_enorm + c * NT + tx * 8 + 4);
        __syncthreads();

        // ---- k-loop: 16 units of 4 dims; 64 FMA2 per unit ----
        unsigned long long acc[4][8];
        #pragma unroll
        for (int i = 0; i < 4; i++)
            #pragma unroll
            for (int j = 0; j < 8; j++) acc[i][j] = 0ull;

        #pragma unroll 8
        for (int u = 0; u < 16; u++) {
            const int suz = swz(u, ty);   // m>>2 == ty for all 4 m's
            const int sue = swz(u, tx);   // n>>3 == tx for all 8 n's
            ulonglong2 zv[4];
            #pragma unroll
            for (int i = 0; i < 4; i++)
                zv[i] = *(const ulonglong2*)(z_s + (ty * 4 + i) * D_DIM + suz * 4);
            #pragma unroll
            for (int j = 0; j < 8; j++) {
                ulonglong2 ev = *(const ulonglong2*)(e_s + (tx * 8 + j) * D_DIM + sue * 4);
                #pragma unroll
                for (int i = 0; i < 4; i++) {
                    FMA2(acc[i][j], zv[i].x, ev.x);
                    FMA2(acc[i][j], zv[i].y, ev.y);
                }
            }
        }

        // ---- scores + running argmin (ascending n within thread) ----
        float en[8] = {en0.x, en0.y, en0.z, en0.w, en1.x, en1.y, en1.z, en1.w};
        #pragma unroll
        for (int j = 0; j < 8; j++) {
            int nidx = c * NT + tx * 8 + j;
            #pragma unroll
            for (int i = 0; i < 4; i++) {
                float dot = f32x2_hsum(acc[i][j]);
                float s = fmaf(-2.f, dot, en[j]);
                if (s < best[i]) { best[i] = s; bidx[i] = nidx; }
            }
        }
    }

    // ---- cross-lane argmin within 8-lane tx-groups (same ty) ----
    #pragma unroll
    for (int i = 0; i < 4; i++) {
        float s = best[i]; int b = bidx[i];
        #pragma unroll
        for (int off = 4; off > 0; off >>= 1) {
            float s2 = __shfl_xor_sync(0xffffffffu, s, off, 8);
            int   b2 = __shfl_xor_sync(0xffffffffu, b, off, 8);
            if (s2 < s || (s2 == s && b2 < b)) { s = s2; b = b2; }
        }
        if (tx == 0) s_bidx[ty * 4 + i] = b;
    }
    __syncthreads();

    // ---- epilogue: 64 points x 16 float4-units, 8 per thread ----
    float lsum = 0.f;
    #pragma unroll
    for (int r = 0; r < 8; r++) {
        int id = t + BLOCK * r;
        int p = id >> 4, q = id & 15;
        int b = s_bidx[p];
        int pt = pt0 + p;
        float4 qv = *(const float4*)(emb + (size_t)b * D_DIM + q * 4);
        float4 zv = *(const float4*)(z_s + p * D_DIM + swz(q, p >> 2) * 4);
        *(float4*)(out_zq + (size_t)pt * D_DIM + q * 4) = qv;
        float dx = zv.x - qv.x, dy = zv.y - qv.y;
        float dz2 = zv.z - qv.z, dw = zv.w - qv.w;
        lsum += dx * dx + dy * dy + dz2 * dz2 + dw * dw;
        float* esum = g_embed_sum + (size_t)b * D_DIM + q * 4;
        atomicAdd(esum + 0, zv.x);
        atomicAdd(esum + 1, zv.y);
        atomicAdd(esum + 2, zv.z);
        atomicAdd(esum + 3, zv.w);
        if (q == 0) {
            out_idx[pt] = (float)b;
            atomicAdd(&g_counts[b], 1.f);
        }
    }

    sred[t] = lsum;
    __syncthreads();
    for (int s = BLOCK / 2; s > 0; s >>= 1) {
        if (t < s) sred[t] += sred[t + s];
        __syncthreads();
    }
    if (t == 0) atomicAdd(&g_loss_sum, sred[0]);
}

// -------- finalize: EMA updates, normalization, loss mean --------
__global__ __launch_bounds__(1024) void finalize_kernel(
    const float* __restrict__ cluster_size, const float* __restrict__ ema,
    float* __restrict__ out_loss, float* __restrict__ out_nemb,
    float* __restrict__ out_ncs, float* __restrict__ out_nema)
{
    __shared__ float sred[1024];
    const int t = threadIdx.x;   // one CTA, 1024 threads (== K)

    float c = cluster_size[t] * DECAY + ONE_MINUS_DECAY * g_counts[t];
    out_ncs[t] = c;
    sred[t] = c;
    __syncthreads();
    for (int s = 512; s > 0; s >>= 1) {
        if (t < s) sred[t] += sred[t + s];
        __syncthreads();
    }
    float n = sred[0];
    float cs = (c + EPSV) / (n + (float)K_EMB * EPSV) * n;
    float inv = 1.f / cs;

    #pragma unroll 4
    for (int q = 0; q < D_DIM; q++) {
        int idx = t * D_DIM + q;
        float s = ema[idx] * DECAY + ONE_MINUS_DECAY * g_embed_sum[idx];
        out_nema[idx] = s;
        out_nemb[idx] = s * inv;
    }
    if (t == 0) out_loss[0] = g_loss_sum / (float)((size_t)N_PTS * D_DIM);
}

// -------- launch --------
extern "C" void kernel_launch(void* const* d_in, const int* in_sizes, int n_in,
                              void* d_out, int out_size) {
    const float* z   = (const float*)d_in[0];
    const float* emb = (const float*)d_in[1];
    const float* cs  = (const float*)d_in[2];
    const float* ema = (const float*)d_in[3];

    float* out      = (float*)d_out;
    float* out_zq   = out;                               // N*D
    float* out_loss = out + (size_t)N_PTS * D_DIM;       // 1
    float* out_idx  = out_loss + 1;                      // N
    float* out_nemb = out_idx + N_PTS;                   // K*D
    float* out_ncs  = out_nemb + (size_t)K_EMB * D_DIM;  // K
    float* out_nema = out_ncs + K_EMB;                   // K*D

    prep_kernel<<<256, 256>>>(emb);
    vq_main<<<N_PTS / MT, BLOCK>>>(z, emb, out_zq, out_idx);
    finalize_kernel<<<1, 1024>>>(cs, ema, out_loss, out_nemb, out_ncs, out_nema);
}

// round 6
// speedup vs baseline: 2.1067x; 1.3093x over previous
#include <cuda_runtime.h>
#include <cuda_bf16.h>
#include <float.h>
#include <cstdint>

#define N_PTS 131072
#define K_EMB 1024
#define D_DIM 64
#define MT    128          // points per CTA
#define NT    64           // embeddings per chunk
#define NCHUNK (K_EMB / NT)
#define BLOCK 256

#define DECAY 0.99f
#define ONE_MINUS_DECAY (1.0f - 0.99f)
#define EPSV 1e-5f

__device__ __forceinline__ uint32_t smem_u32(const void* p) {
    uint32_t a;
    asm("{ .reg .u64 t; cvta.to.shared.u64 t, %1; cvt.u32.u64 %0, t; }"
        : "=r"(a) : "l"(p));
    return a;
}

#define LDMATRIX_X4(r0, r1, r2, r3, addr) \
    asm volatile("ldmatrix.sync.aligned.m8n8.x4.shared.b16 {%0,%1,%2,%3}, [%4];" \
                 : "=r"(r0), "=r"(r1), "=r"(r2), "=r"(r3) : "r"(addr))

#define MMA_BF16(d, a0, a1, a2, a3, b0, b1) \
    asm volatile("mma.sync.aligned.m16n8k16.row.col.f32.bf16.bf16.f32 " \
                 "{%0,%1,%2,%3}, {%4,%5,%6,%7}, {%8,%9}, {%0,%1,%2,%3};" \
                 : "+f"((d)[0]), "+f"((d)[1]), "+f"((d)[2]), "+f"((d)[3]) \
                 : "r"(a0), "r"(a1), "r"(a2), "r"(a3), "r"(b0), "r"(b1))

// -------- scratch (device globals) --------
__device__ float g_counts[K_EMB];
__device__ float g_embed_sum[K_EMB * D_DIM];
__device__ float g_enorm[K_EMB];
__device__ float g_loss_sum;
__device__ __nv_bfloat16 g_eb[3][K_EMB * D_DIM];   // 3-way bf16 split of embeddings

// -------- prep: zero scratch, ||e||^2, bf16 3-split --------
__global__ void prep_kernel(const float* __restrict__ emb) {
    int t = blockIdx.x * blockDim.x + threadIdx.x;   // 65536 threads
    if (t < K_EMB * D_DIM) {
        g_embed_sum[t] = 0.f;
        float v = emb[t];
        __nv_bfloat16 b1 = __float2bfloat16(v);
        float r1 = v - __bfloat162float(b1);
        __nv_bfloat16 b2 = __float2bfloat16(r1);
        float r2 = r1 - __bfloat162float(b2);
        g_eb[0][t] = b1; g_eb[1][t] = b2; g_eb[2][t] = __float2bfloat16(r2);
    }
    if (t < K_EMB) {
        g_counts[t] = 0.f;
        const float4* row = (const float4*)(emb + (size_t)t * D_DIM);
        float s = 0.f;
        #pragma unroll
        for (int q = 0; q < 16; q++) {
            float4 v = row[q];
            s += v.x * v.x + v.y * v.y + v.z * v.z + v.w * v.w;
        }
        g_enorm[t] = s;
    }
    if (t == 0) g_loss_sum = 0.f;
}

// -------- main: HMMA scores + argmin + epilogue --------
__global__ __launch_bounds__(BLOCK) void vq_main(
    const float* __restrict__ z, const float* __restrict__ emb,
    float* __restrict__ out_zq, float* __restrict__ out_idx)
{
    __shared__ __align__(16) unsigned char zb[MT * 128];       // 16KB bf16 staging (1 split)
    __shared__ __align__(16) unsigned char b_s[3 * NT * 128];  // 24KB B chunk, 3 splits
    __shared__ float enorm_s[NT];
    __shared__ int   s_bidx[MT];
    __shared__ float sred[BLOCK];

    const int t    = threadIdx.x;
    const int warp = t >> 5, lane = t & 31;
    const int g    = lane >> 2, tc = lane & 3;
    const int pt0  = blockIdx.x * MT;

    // ======== A: z 3-split bf16 -> ldmatrix fragments (held in regs all kernel) ========
    uint32_t afrag[3][4][4];   // [split][kstep][reg]
    {
        float v[32];
        const int row  = t >> 1;            // 0..127
        const int colh = (t & 1) * 32;      // column half
        {
            const float4* zg = (const float4*)(z + (size_t)(pt0 + row) * D_DIM + colh);
            #pragma unroll
            for (int q = 0; q < 8; q++) {
                float4 w = zg[q];
                v[4 * q] = w.x; v[4 * q + 1] = w.y; v[4 * q + 2] = w.z; v[4 * q + 3] = w.w;
            }
        }
        const uint32_t zb0 = smem_u32(zb);
        #pragma unroll
        for (int s = 0; s < 3; s++) {
            #pragma unroll
            for (int u4 = 0; u4 < 4; u4++) {            // 4 uint4 units of 8 bf16
                uint32_t w[4];
                #pragma unroll
                for (int h = 0; h < 4; h++) {
                    int j = u4 * 8 + 2 * h;
                    __nv_bfloat16 b0 = __float2bfloat16(v[j]);
                    __nv_bfloat16 b1 = __float2bfloat16(v[j + 1]);
                    w[h] = ((uint32_t)__bfloat16_as_ushort(b1) << 16)
                         | (uint32_t)__bfloat16_as_ushort(b0);
                    v[j]     -= __bfloat162float(b0);
                    v[j + 1] -= __bfloat162float(b1);
                }
                int unit = (colh >> 3) + u4;             // 0..7
                *(uint4*)(zb + row * 128 + ((unit ^ (row & 7)) << 4)) =
                    make_uint4(w[0], w[1], w[2], w[3]);
            }
            __syncthreads();
            // per-warp ldmatrix of its 16 rows
            const int wbase = warp * 16;
            const int rl = wbase + (lane & 15);
            #pragma unroll
            for (int ks = 0; ks < 4; ks++) {
                int unit = ks * 2 + (lane >> 4);
                uint32_t addr = zb0 + rl * 128 + ((unit ^ (rl & 7)) << 4);
                LDMATRIX_X4(afrag[s][ks][0], afrag[s][ks][1],
                            afrag[s][ks][2], afrag[s][ks][3], addr);
            }
            __syncthreads();
        }
    }

    // product terms (a_split, b_split): 11,12,21,22,13,31
    const int TA[6] = {0, 0, 1, 1, 0, 2};
    const int TB[6] = {0, 1, 0, 1, 2, 0};
    const uint32_t bs0 = smem_u32(b_s);

    float best0 = FLT_MAX, best1 = FLT_MAX;
    int   bidx0 = 0,       bidx1 = 0;

    for (int c = 0; c < NCHUNK; c++) {
        __syncthreads();   // previous chunk's readers done
        // ---- stage B chunk: 3 splits x 64 rows x 128B, XOR-swizzled ----
        #pragma unroll
        for (int r = 0; r < 6; r++) {
            int id = t + BLOCK * r;              // 0..1535 16B-units
            int sp = id >> 9, rw = (id >> 3) & 63, u = id & 7;
            uint4 w = *(const uint4*)((const unsigned char*)&g_eb[sp][(size_t)c * NT * D_DIM]
                                      + rw * 128 + u * 16);
            *(uint4*)(b_s + sp * 8192 + rw * 128 + ((u ^ (rw & 7)) << 4)) = w;
        }
        if (t < NT) enorm_s[t] = g_enorm[c * NT + t];
        __syncthreads();

        float acc[8][4];
        #pragma unroll
        for (int nt = 0; nt < 8; nt++)
            #pragma unroll
            for (int i = 0; i < 4; i++) acc[nt][i] = 0.f;

        #pragma unroll
        for (int p = 0; p < 6; p++) {
            const uint32_t bbase = bs0 + TB[p] * 8192;
            #pragma unroll
            for (int kh = 0; kh < 2; kh++) {     // k halves: units 0-3 / 4-7
                uint32_t bb[8][4];
                #pragma unroll
                for (int nt = 0; nt < 8; nt++) {
                    int rw = nt * 8 + (lane & 7);
                    int unit = kh * 4 + (lane >> 3);
                    uint32_t addr = bbase + rw * 128 + ((unit ^ (rw & 7)) << 4);
                    LDMATRIX_X4(bb[nt][0], bb[nt][1], bb[nt][2], bb[nt][3], addr);
                }
                #pragma unroll
                for (int ks = 0; ks < 2; ks++) {
                    const uint32_t* a = afrag[TA[p]][kh * 2 + ks];
                    #pragma unroll
                    for (int nt = 0; nt < 8; nt++)   // 8 independent acc chains
                        MMA_BF16(acc[nt], a[0], a[1], a[2], a[3],
                                 bb[nt][ks * 2], bb[nt][ks * 2 + 1]);
                }
            }
        }

        // ---- scores + running argmin ----
        #pragma unroll
        for (int nt = 0; nt < 8; nt++) {
            int nl = nt * 8 + 2 * tc;
            int n0 = c * NT + nl;
            float e0 = enorm_s[nl], e1 = enorm_s[nl + 1];
            float s00 = fmaf(-2.f, acc[nt][0], e0);
            float s01 = fmaf(-2.f, acc[nt][1], e1);
            float s10 = fmaf(-2.f, acc[nt][2], e0);
            float s11 = fmaf(-2.f, acc[nt][3], e1);
            if (s00 < best0) { best0 = s00; bidx0 = n0; }
            if (s01 < best0) { best0 = s01; bidx0 = n0 + 1; }
            if (s10 < best1) { best1 = s10; bidx1 = n0; }
            if (s11 < best1) { best1 = s11; bidx1 = n0 + 1; }
        }
    }

    // ---- quad reduction (lanes sharing g), tie-break toward smaller index ----
    #pragma unroll
    for (int off = 1; off <= 2; off <<= 1) {
        float s0 = __shfl_xor_sync(0xffffffffu, best0, off);
        int   b0 = __shfl_xor_sync(0xffffffffu, bidx0, off);
        if (s0 < best0 || (s0 == best0 && b0 < bidx0)) { best0 = s0; bidx0 = b0; }
        float s1 = __shfl_xor_sync(0xffffffffu, best1, off);
        int   b1 = __shfl_xor_sync(0xffffffffu, bidx1, off);
        if (s1 < best1 || (s1 == best1 && b1 < bidx1)) { best1 = s1; bidx1 = b1; }
    }
    if (tc == 0) {
        s_bidx[warp * 16 + g]     = bidx0;
        s_bidx[warp * 16 + g + 8] = bidx1;
    }
    __syncthreads();

    // ---- epilogue ----
    if (t < MT) {
        int b = s_bidx[t];
        out_idx[pt0 + t] = (float)b;
        atomicAdd(&g_counts[b], 1.f);
    }

    float lsum = 0.f;
    #pragma unroll
    for (int r = 0; r < 8; r++) {
        int id = t + BLOCK * r;          // 128 pts x 16 float4-units
        int p = id >> 4, q = id & 15;
        int b = s_bidx[p];
        int pt = pt0 + p;
        float4 qv = *(const float4*)(emb + (size_t)b * D_DIM + q * 4);
        float4 zv = *(const float4*)(z + (size_t)pt * D_DIM + q * 4);
        *(float4*)(out_zq + (size_t)pt * D_DIM + q * 4) = qv;
        float dx = zv.x - qv.x, dy = zv.y - qv.y;
        float dz2 = zv.z - qv.z, dw = zv.w - qv.w;
        lsum += dx * dx + dy * dy + dz2 * dz2 + dw * dw;
        float* esum = g_embed_sum + (size_t)b * D_DIM + q * 4;
        atomicAdd(esum + 0, zv.x);
        atomicAdd(esum + 1, zv.y);
        atomicAdd(esum + 2, zv.z);
        atomicAdd(esum + 3, zv.w);
    }

    sred[t] = lsum;
    __syncthreads();
    for (int s = BLOCK / 2; s > 0; s >>= 1) {
        if (t < s) sred[t] += sred[t + s];
        __syncthreads();
    }
    if (t == 0) atomicAdd(&g_loss_sum, sred[0]);
}

// -------- finalize: EMA updates, normalization, loss mean --------
__global__ __launch_bounds__(1024) void finalize_kernel(
    const float* __restrict__ cluster_size, const float* __restrict__ ema,
    float* __restrict__ out_loss, float* __restrict__ out_nemb,
    float* __restrict__ out_ncs, float* __restrict__ out_nema)
{
    __shared__ float sred[1024];
    const int t = threadIdx.x;   // one CTA, 1024 threads (== K)

    float c = cluster_size[t] * DECAY + ONE_MINUS_DECAY * g_counts[t];
    out_ncs[t] = c;
    sred[t] = c;
    __syncthreads();
    for (int s = 512; s > 0; s >>= 1) {
        if (t < s) sred[t] += sred[t + s];
        __syncthreads();
    }
    float n = sred[0];
    float cs = (c + EPSV) / (n + (float)K_EMB * EPSV) * n;
    float inv = 1.f / cs;

    #pragma unroll 4
    for (int q = 0; q < D_DIM; q++) {
        int idx = t * D_DIM + q;
        float s = ema[idx] * DECAY + ONE_MINUS_DECAY * g_embed_sum[idx];
        out_nema[idx] = s;
        out_nemb[idx] = s * inv;
    }
    if (t == 0) out_loss[0] = g_loss_sum / (float)((size_t)N_PTS * D_DIM);
}

// -------- launch --------
extern "C" void kernel_launch(void* const* d_in, const int* in_sizes, int n_in,
                              void* d_out, int out_size) {
    const float* z   = (const float*)d_in[0];
    const float* emb = (const float*)d_in[1];
    const float* cs  = (const float*)d_in[2];
    const float* ema = (const float*)d_in[3];

    float* out      = (float*)d_out;
    float* out_zq   = out;                               // N*D
    float* out_loss = out + (size_t)N_PTS * D_DIM;       // 1
    float* out_idx  = out_loss + 1;                      // N
    float* out_nemb = out_idx + N_PTS;                   // K*D
    float* out_ncs  = out_nemb + (size_t)K_EMB * D_DIM;  // K
    float* out_nema = out_ncs + K_EMB;                   // K*D

    prep_kernel<<<256, 256>>>(emb);
    vq_main<<<N_PTS / MT, BLOCK>>>(z, emb, out_zq, out_idx);
    finalize_kernel<<<1, 1024>>>(cs, ema, out_loss, out_nemb, out_ncs, out_nema);
}

// round 7
// speedup vs baseline: 2.2574x; 1.0715x over previous
#include <cuda_runtime.h>
#include <cuda_bf16.h>
#include <float.h>
#include <cstdint>

#define N_PTS 131072
#define K_EMB 1024
#define D_DIM 64
#define MT    128          // points per CTA
#define NT    64           // embeddings per chunk
#define NCHUNK (K_EMB / NT)
#define BLOCK 256
#define BUFB  (3 * 8192)   // bytes per B buffer (3 splits x 64x64 bf16)

#define DECAY 0.99f
#define ONE_MINUS_DECAY (1.0f - 0.99f)
#define EPSV 1e-5f

__device__ __forceinline__ uint32_t smem_u32(const void* p) {
    uint32_t a;
    asm("{ .reg .u64 t; cvta.to.shared.u64 t, %1; cvt.u32.u64 %0, t; }"
        : "=r"(a) : "l"(p));
    return a;
}

#define LDMATRIX_X4(r0, r1, r2, r3, addr) \
    asm volatile("ldmatrix.sync.aligned.m8n8.x4.shared.b16 {%0,%1,%2,%3}, [%4];" \
                 : "=r"(r0), "=r"(r1), "=r"(r2), "=r"(r3) : "r"(addr))

#define MMA_BF16(d, a0, a1, a2, a3, b0, b1) \
    asm volatile("mma.sync.aligned.m16n8k16.row.col.f32.bf16.bf16.f32 " \
                 "{%0,%1,%2,%3}, {%4,%5,%6,%7}, {%8,%9}, {%0,%1,%2,%3};" \
                 : "+f"((d)[0]), "+f"((d)[1]), "+f"((d)[2]), "+f"((d)[3]) \
                 : "r"(a0), "r"(a1), "r"(a2), "r"(a3), "r"(b0), "r"(b1))

#define CP_ASYNC16(dst, src) \
    asm volatile("cp.async.cg.shared.global [%0], [%1], 16;" \
                 :: "r"(dst), "l"(src) : "memory")
#define CP_COMMIT() asm volatile("cp.async.commit_group;" ::: "memory")
#define CP_WAIT1()  asm volatile("cp.async.wait_group 1;" ::: "memory")
#define CP_WAIT0()  asm volatile("cp.async.wait_group 0;" ::: "memory")

// -------- scratch (device globals) --------
__device__ float g_counts[K_EMB];
__device__ float g_embed_sum[K_EMB * D_DIM];
__device__ float g_enorm[K_EMB];
__device__ float g_loss_sum;
__device__ __nv_bfloat16 g_eb[3][K_EMB * D_DIM];   // 3-way bf16 split of embeddings

// -------- prep: zero scratch, ||e||^2, bf16 3-split --------
__global__ void prep_kernel(const float* __restrict__ emb) {
    int t = blockIdx.x * blockDim.x + threadIdx.x;   // 65536 threads
    if (t < K_EMB * D_DIM) {
        g_embed_sum[t] = 0.f;
        float v = emb[t];
        __nv_bfloat16 b1 = __float2bfloat16(v);
        float r1 = v - __bfloat162float(b1);
        __nv_bfloat16 b2 = __float2bfloat16(r1);
        float r2 = r1 - __bfloat162float(b2);
        g_eb[0][t] = b1; g_eb[1][t] = b2; g_eb[2][t] = __float2bfloat16(r2);
    }
    if (t < K_EMB) {
        g_counts[t] = 0.f;
        const float4* row = (const float4*)(emb + (size_t)t * D_DIM);
        float s = 0.f;
        #pragma unroll
        for (int q = 0; q < 16; q++) {
            float4 v = row[q];
            s += v.x * v.x + v.y * v.y + v.z * v.z + v.w * v.w;
        }
        g_enorm[t] = s;
    }
    if (t == 0) g_loss_sum = 0.f;
}

// -------- main: HMMA scores (double-buffered cp.async) + argmin + epilogue --------
// dynamic smem layout:
//   [0, 2*BUFB)            B double buffer (buf1 aliased as z staging in prologue)
//   [2*BUFB, +512)         enorm double buffer (2 x 64 floats)
//   [.., +512)             s_bidx (128 ints)
//   [.., +1024)            sred (256 floats)
#define SMEM_TOTAL (2 * BUFB + 512 + 512 + 1024)

__global__ __launch_bounds__(BLOCK, 2) void vq_main(
    const float* __restrict__ z, const float* __restrict__ emb,
    float* __restrict__ out_zq, float* __restrict__ out_idx)
{
    extern __shared__ __align__(16) unsigned char smem[];
    unsigned char* b_s   = smem;
    float*         enorm = (float*)(smem + 2 * BUFB);
    int*           s_bidx = (int*)(smem + 2 * BUFB + 512);
    float*         sred  = (float*)(smem + 2 * BUFB + 1024);
    unsigned char* zb    = smem + BUFB;          // aliases buffer 1 (prologue only)

    const int t    = threadIdx.x;
    const int warp = t >> 5, lane = t & 31;
    const int g    = lane >> 2, tc = lane & 3;
    const int pt0  = blockIdx.x * MT;
    const uint32_t bs0    = smem_u32(b_s);
    const uint32_t enorm0 = smem_u32(enorm);

    // ---- async stage of chunk c into buffer buf ----
    auto stage = [&](int c, int buf) {
        #pragma unroll
        for (int r = 0; r < 6; r++) {
            int id = t + BLOCK * r;              // 0..1535 16B-units
            int sp = id >> 9, rw = (id >> 3) & 63, u = id & 7;
            const unsigned char* src = (const unsigned char*)g_eb[sp]
                                     + (size_t)c * 8192 + rw * 128 + u * 16;
            uint32_t dst = bs0 + buf * BUFB + sp * 8192 + rw * 128
                         + ((u ^ (rw & 7)) << 4);
            CP_ASYNC16(dst, src);
        }
        if (t < 16) {
            const unsigned char* src = (const unsigned char*)(g_enorm + c * NT) + t * 16;
            CP_ASYNC16(enorm0 + buf * 256 + t * 16, src);
        }
    };

    // kick off chunk 0 into buffer 0 (latency hidden behind A prologue)
    stage(0, 0);
    CP_COMMIT();

    // ======== A: z 3-split bf16 -> ldmatrix fragments (held in regs) ========
    uint32_t afrag[3][4][4];   // [split][kstep][reg]
    {
        float v[32];
        const int row  = t >> 1;            // 0..127
        const int colh = (t & 1) * 32;      // column half
        {
            const float4* zg = (const float4*)(z + (size_t)(pt0 + row) * D_DIM + colh);
            #pragma unroll
            for (int q = 0; q < 8; q++) {
                float4 w = zg[q];
                v[4 * q] = w.x; v[4 * q + 1] = w.y; v[4 * q + 2] = w.z; v[4 * q + 3] = w.w;
            }
        }
        const uint32_t zb0 = smem_u32(zb);
        #pragma unroll
        for (int s = 0; s < 3; s++) {
            #pragma unroll
            for (int u4 = 0; u4 < 4; u4++) {            // 4 uint4 units of 8 bf16
                uint32_t w[4];
                #pragma unroll
                for (int h = 0; h < 4; h++) {
                    int j = u4 * 8 + 2 * h;
                    __nv_bfloat16 b0 = __float2bfloat16(v[j]);
                    __nv_bfloat16 b1 = __float2bfloat16(v[j + 1]);
                    w[h] = ((uint32_t)__bfloat16_as_ushort(b1) << 16)
                         | (uint32_t)__bfloat16_as_ushort(b0);
                    v[j]     -= __bfloat162float(b0);
                    v[j + 1] -= __bfloat162float(b1);
                }
                int unit = (colh >> 3) + u4;             // 0..7
                *(uint4*)(zb + row * 128 + ((unit ^ (row & 7)) << 4)) =
                    make_uint4(w[0], w[1], w[2], w[3]);
            }
            __syncthreads();
            const int rl = warp * 16 + (lane & 15);
            #pragma unroll
            for (int ks = 0; ks < 4; ks++) {
                int unit = ks * 2 + (lane >> 4);
                uint32_t addr = zb0 + rl * 128 + ((unit ^ (rl & 7)) << 4);
                LDMATRIX_X4(afrag[s][ks][0], afrag[s][ks][1],
                            afrag[s][ks][2], afrag[s][ks][3], addr);
            }
            __syncthreads();
        }
    }

    // b-split s is consumed by a-splits: s=0 -> {0,1,2}; s=1 -> {0,1}; s=2 -> {0}
    const int NUSE[3] = {3, 2, 1};

    float best0 = FLT_MAX, best1 = FLT_MAX;
    int   bidx0 = 0,       bidx1 = 0;

    for (int c = 0; c < NCHUNK; c++) {
        const int cur = c & 1;
        if (c + 1 < NCHUNK) {            // prefetch next chunk into other buffer
            stage(c + 1, cur ^ 1);
            CP_COMMIT();
            CP_WAIT1();                  // chunk c's group complete
        } else {
            CP_WAIT0();
        }
        __syncthreads();                 // chunk c visible to all warps

        float acc[8][4];
        #pragma unroll
        for (int nt = 0; nt < 8; nt++)
            #pragma unroll
            for (int i = 0; i < 4; i++) acc[nt][i] = 0.f;

        #pragma unroll
        for (int s = 0; s < 3; s++) {
            const uint32_t bbase = bs0 + cur * BUFB + s * 8192;
            #pragma unroll
            for (int kh = 0; kh < 2; kh++) {     // k halves: units 0-3 / 4-7
                uint32_t bb[8][4];
                #pragma unroll
                for (int nt = 0; nt < 8; nt++) {
                    int rw = nt * 8 + (lane & 7);
                    int unit = kh * 4 + (lane >> 3);
                    uint32_t addr = bbase + rw * 128 + ((unit ^ (rw & 7)) << 4);
                    LDMATRIX_X4(bb[nt][0], bb[nt][1], bb[nt][2], bb[nt][3], addr);
                }
                #pragma unroll
                for (int a = 0; a < 3; a++) {
                    if (a < NUSE[s]) {
                        #pragma unroll
                        for (int ks = 0; ks < 2; ks++) {
                            const uint32_t* af = afrag[a][kh * 2 + ks];
                            #pragma unroll
                            for (int nt = 0; nt < 8; nt++)   // 8 independent chains
                                MMA_BF16(acc[nt], af[0], af[1], af[2], af[3],
                                         bb[nt][ks * 2], bb[nt][ks * 2 + 1]);
                        }
                    }
                }
            }
        }

        // ---- scores + running argmin ----
        const float* en = enorm + cur * 64;
        #pragma unroll
        for (int nt = 0; nt < 8; nt++) {
            int nl = nt * 8 + 2 * tc;
            int n0 = c * NT + nl;
            float e0 = en[nl], e1 = en[nl + 1];
            float s00 = fmaf(-2.f, acc[nt][0], e0);
            float s01 = fmaf(-2.f, acc[nt][1], e1);
            float s10 = fmaf(-2.f, acc[nt][2], e0);
            float s11 = fmaf(-2.f, acc[nt][3], e1);
            if (s00 < best0) { best0 = s00; bidx0 = n0; }
            if (s01 < best0) { best0 = s01; bidx0 = n0 + 1; }
            if (s10 < best1) { best1 = s10; bidx1 = n0; }
            if (s11 < best1) { best1 = s11; bidx1 = n0 + 1; }
        }
        __syncthreads();   // all readers done before buffer reuse next iter
    }

    // ---- quad reduction (lanes sharing g), tie-break toward smaller index ----
    #pragma unroll
    for (int off = 1; off <= 2; off <<= 1) {
        float s0 = __shfl_xor_sync(0xffffffffu, best0, off);
        int   b0 = __shfl_xor_sync(0xffffffffu, bidx0, off);
        if (s0 < best0 || (s0 == best0 && b0 < bidx0)) { best0 = s0; bidx0 = b0; }
        float s1 = __shfl_xor_sync(0xffffffffu, best1, off);
        int   b1 = __shfl_xor_sync(0xffffffffu, bidx1, off);
        if (s1 < best1 || (s1 == best1 && b1 < bidx1)) { best1 = s1; bidx1 = b1; }
    }
    if (tc == 0) {
        s_bidx[warp * 16 + g]     = bidx0;
        s_bidx[warp * 16 + g + 8] = bidx1;
    }
    __syncthreads();

    // ---- epilogue ----
    if (t < MT) {
        int b = s_bidx[t];
        out_idx[pt0 + t] = (float)b;
        atomicAdd(&g_counts[b], 1.f);
    }

    float lsum = 0.f;
    #pragma unroll
    for (int r = 0; r < 8; r++) {
        int id = t + BLOCK * r;          // 128 pts x 16 float4-units
        int p = id >> 4, q = id & 15;
        int b = s_bidx[p];
        int pt = pt0 + p;
        float4 qv = *(const float4*)(emb + (size_t)b * D_DIM + q * 4);
        float4 zv = *(const float4*)(z + (size_t)pt * D_DIM + q * 4);
        *(float4*)(out_zq + (size_t)pt * D_DIM + q * 4) = qv;
        float dx = zv.x - qv.x, dy = zv.y - qv.y;
        float dz2 = zv.z - qv.z, dw = zv.w - qv.w;
        lsum += dx * dx + dy * dy + dz2 * dz2 + dw * dw;
        float* esum = g_embed_sum + (size_t)b * D_DIM + q * 4;
        atomicAdd(esum + 0, zv.x);
        atomicAdd(esum + 1, zv.y);
        atomicAdd(esum + 2, zv.z);
        atomicAdd(esum + 3, zv.w);
    }

    sred[t] = lsum;
    __syncthreads();
    for (int s = BLOCK / 2; s > 0; s >>= 1) {
        if (t < s) sred[t] += sred[t + s];
        __syncthreads();
    }
    if (t == 0) atomicAdd(&g_loss_sum, sred[0]);
}

// -------- finalize: EMA updates, normalization, loss mean --------
__global__ __launch_bounds__(1024) void finalize_kernel(
    const float* __restrict__ cluster_size, const float* __restrict__ ema,
    float* __restrict__ out_loss, float* __restrict__ out_nemb,
    float* __restrict__ out_ncs, float* __restrict__ out_nema)
{
    __shared__ float sred[1024];
    const int t = threadIdx.x;   // one CTA, 1024 threads (== K)

    float c = cluster_size[t] * DECAY + ONE_MINUS_DECAY * g_counts[t];
    out_ncs[t] = c;
    sred[t] = c;
    __syncthreads();
    for (int s = 512; s > 0; s >>= 1) {
        if (t < s) sred[t] += sred[t + s];
        __syncthreads();
    }
    float n = sred[0];
    float cs = (c + EPSV) / (n + (float)K_EMB * EPSV) * n;
    float inv = 1.f / cs;

    #pragma unroll 4
    for (int q = 0; q < D_DIM; q++) {
        int idx = t * D_DIM + q;
        float s = ema[idx] * DECAY + ONE_MINUS_DECAY * g_embed_sum[idx];
        out_nema[idx] = s;
        out_nemb[idx] = s * inv;
    }
    if (t == 0) out_loss[0] = g_loss_sum / (float)((size_t)N_PTS * D_DIM);
}

// -------- launch --------
extern "C" void kernel_launch(void* const* d_in, const int* in_sizes, int n_in,
                              void* d_out, int out_size) {
    const float* z   = (const float*)d_in[0];
    const float* emb = (const float*)d_in[1];
    const float* cs  = (const float*)d_in[2];
    const float* ema = (const float*)d_in[3];

    float* out      = (float*)d_out;
    float* out_zq   = out;                               // N*D
    float* out_loss = out + (size_t)N_PTS * D_DIM;       // 1
    float* out_idx  = out_loss + 1;                      // N
    float* out_nemb = out_idx + N_PTS;                   // K*D
    float* out_ncs  = out_nemb + (size_t)K_EMB * D_DIM;  // K
    float* out_nema = out_ncs + K_EMB;                   // K*D

    cudaFuncSetAttribute(vq_main, cudaFuncAttributeMaxDynamicSharedMemorySize,
                         SMEM_TOTAL);

    prep_kernel<<<256, 256>>>(emb);
    vq_main<<<N_PTS / MT, BLOCK, SMEM_TOTAL>>>(z, emb, out_zq, out_idx);
    finalize_kernel<<<1, 1024>>>(cs, ema, out_loss, out_nemb, out_ncs, out_nema);
}